// round 9
// baseline (speedup 1.0000x reference)
#include <cuda_runtime.h>
#include <cuda_bf16.h>

// loss[s] = -(1/496)*[ sum_i x_i*(31-i) - sum_{i<j} ln(e_i+e_j) + 0.0005*sum_i x_i^2*(31-2i) ]
// via log_sigmoid(x_i - x_j) == x_i - ln(e^{x_i} + e^{x_j}).
//
// sum_{pairs} ln = ln(prod): per lane ONE 16-term fp32 product of
// (e_i+e_j)/4 terms (2^-2 prescale keeps the exponent in range; correction
// and the -127 bias fold into one per-lane constant), one lg2 at the end.
//
// Fully scalar, 4 segments/warp as 4 independent chains. ONE combined float4
// ring: a single LDS.128 per offset feeds all 4 chains. 256-thread blocks
// for high occupancy.

static constexpr float INV_PAIRS = 1.0f / 496.0f;
static constexpr float LN2  = 0.69314718055994530942f;
static constexpr float L2E  = 1.44269504088896340736f;
static constexpr int   WPB  = 8;                 // warps per block (256 thr)
static constexpr int   SEG_PER_BLOCK = WPB * 4;  // 32

typedef unsigned int u32;

__device__ __forceinline__ float ex2(float x) {
    float r; asm("ex2.approx.f32 %0,%1;" : "=f"(r) : "f"(x)); return r;
}
__device__ __forceinline__ float lg2(float x) {
    float r; asm("lg2.approx.f32 %0,%1;" : "=f"(r) : "f"(x)); return r;
}

__global__ __launch_bounds__(WPB * 32)
void rmloss_kernel(const float* __restrict__ logits,
                   float4* __restrict__ out,
                   int n_seg)
{
    __shared__ float4 ring[WPB][64];   // (e0,e1,e2,e3) per lane, duplicated

    const int w    = threadIdx.x >> 5;
    const int lane = threadIdx.x & 31;
    const int gw   = blockIdx.x * WPB + w;
    const int s0   = gw * 4;                        // 4 segments per warp
    if (s0 >= n_seg) return;

    const float* base = logits + (size_t)s0 * 32 + lane;
    const float x0 = base[0],  x1 = base[32];
    const float x2 = base[64], x3 = base[96];

    // e = exp(x) * 2^-2 = exp2(x*log2e - 2): prescale keeps the 16-term
    // product exponent-safe; correction folded into the KPS constant.
    const float e0 = ex2(fmaf(x0, L2E, -2.0f));
    const float e1 = ex2(fmaf(x1, L2E, -2.0f));
    const float e2 = ex2(fmaf(x2, L2E, -2.0f));
    const float e3 = ex2(fmaf(x3, L2E, -2.0f));

    // Duplicated combined ring -> one LDS.128 per offset serves all 4 chains.
    const float4 ev = make_float4(e0, e1, e2, e3);
    ring[w][lane]      = ev;
    ring[w][lane + 32] = ev;
    __syncwarp();

    // Single 16-term product per chain. Offsets 1..15 hit each unordered pair
    // exactly once; offset 16 only lanes 0..15 (upper half multiplies by 1).
    float4 a = ring[w][lane + 1];
    float p0 = e0 + a.x, p1 = e1 + a.y, p2 = e2 + a.z, p3 = e3 + a.w;
    #pragma unroll
    for (int o = 2; o <= 15; ++o) {
        a = ring[w][lane + o];
        p0 *= e0 + a.x;  p1 *= e1 + a.y;
        p2 *= e2 + a.z;  p3 *= e3 + a.w;
    }
    {
        a = ring[w][lane + 16];
        const bool lo16 = (lane < 16);
        p0 *= lo16 ? (e0 + a.x) : 1.0f;
        p1 *= lo16 ? (e1 + a.y) : 1.0f;
        p2 *= lo16 ? (e2 + a.z) : 1.0f;
        p3 *= lo16 ? (e3 + a.w) : 1.0f;
    }

    // Per-lane constants (all scale factors folded in).
    //   partial = x*CL + x^2*CQ + ln2/496 * [ (E - 127) + lg2(m) + 2*n_terms ]
    // KPS absorbs (-127 + 2*n_terms)*CLN.
    const float CL  = (float)(31 - lane)     * (-INV_PAIRS);
    const float CQ  = (float)(31 - 2 * lane) * (-0.0005f * INV_PAIRS);
    const float CLN = LN2 * INV_PAIRS;
    const float KPS = CLN * (((lane < 16) ? 32.0f : 30.0f) - 127.0f);

    // log2(prod) via exponent extraction: E = raw exponent, m in [1,2).
    u32 b0 = __float_as_uint(p0), b1 = __float_as_uint(p1);
    u32 b2 = __float_as_uint(p2), b3 = __float_as_uint(p3);
    const float m0 = __uint_as_float((b0 & 0x007FFFFFu) | 0x3F800000u);
    const float m1 = __uint_as_float((b1 & 0x007FFFFFu) | 0x3F800000u);
    const float m2 = __uint_as_float((b2 & 0x007FFFFFu) | 0x3F800000u);
    const float m3 = __uint_as_float((b3 & 0x007FFFFFu) | 0x3F800000u);

    float t0 = fmaf((float)(int)(b0 >> 23), CLN, KPS);
    float t1 = fmaf((float)(int)(b1 >> 23), CLN, KPS);
    float t2 = fmaf((float)(int)(b2 >> 23), CLN, KPS);
    float t3 = fmaf((float)(int)(b3 >> 23), CLN, KPS);
    t0 = fmaf(lg2(m0), CLN, t0);
    t1 = fmaf(lg2(m1), CLN, t1);
    t2 = fmaf(lg2(m2), CLN, t2);
    t3 = fmaf(lg2(m3), CLN, t3);

    t0 = fmaf(x0, CL, t0);  t0 = fmaf(x0 * x0, CQ, t0);
    t1 = fmaf(x1, CL, t1);  t1 = fmaf(x1 * x1, CQ, t1);
    t2 = fmaf(x2, CL, t2);  t2 = fmaf(x2 * x2, CQ, t2);
    t3 = fmaf(x3, CL, t3);  t3 = fmaf(x3 * x3, CQ, t3);

    // Butterfly reduction: 4 independent scalar chains.
    #pragma unroll
    for (int m = 16; m >= 1; m >>= 1) {
        t0 += __shfl_xor_sync(0xFFFFFFFFu, t0, m);
        t1 += __shfl_xor_sync(0xFFFFFFFFu, t1, m);
        t2 += __shfl_xor_sync(0xFFFFFFFFu, t2, m);
        t3 += __shfl_xor_sync(0xFFFFFFFFu, t3, m);
    }

    if (lane == 0)
        out[gw] = make_float4(t0, t1, t2, t3);   // STG.128, coalesced

}

extern "C" void kernel_launch(void* const* d_in, const int* in_sizes, int n_in,
                              void* d_out, int out_size)
{
    const float* logits = (const float*)d_in[0];
    float4* out = (float4*)d_out;
    const int n_seg = out_size;                  // 32768

    const int threads = WPB * 32;                // 256
    const int blocks = (n_seg + SEG_PER_BLOCK - 1) / SEG_PER_BLOCK;   // 1024
    rmloss_kernel<<<blocks, threads>>>(logits, out, n_seg);
}

// round 11
// speedup vs baseline: 1.0036x; 1.0036x over previous
#include <cuda_runtime.h>
#include <cuda_bf16.h>

// loss[s] = -(1/496)*[ sum_i x_i*(31-i) - sum_{i<j} ln(e_i+e_j) + 0.0005*sum_i x_i^2*(31-2i) ]
// via log_sigmoid(x_i - x_j) == x_i - ln(e^{x_i} + e^{x_j}).
//
// sum_{pairs} ln = ln(prod): per lane ONE 16-term fp32 product of (e_i+e_j)/4
// terms (2^-2 prescale keeps the exponent in range; correction + exponent
// bias fold into one constant), one lg2 at the end.
//
// Scalar, 4 segments/warp, combined float4 ring (1 LDS.128 per offset feeds
// all 4 chains). Lane reduction via warp-level smem transpose (8 lanes per
// segment + 3 shfl_xor) instead of a 5-deep butterfly.

static constexpr float INV_PAIRS = 1.0f / 496.0f;
static constexpr float LN2  = 0.69314718055994530942f;
static constexpr float L2E  = 1.44269504088896340736f;
static constexpr int   WPB  = 8;                 // warps per block (256 thr)
static constexpr int   SEG_PER_BLOCK = WPB * 4;  // 32

typedef unsigned int u32;

__device__ __forceinline__ float ex2(float x) {
    float r; asm("ex2.approx.f32 %0,%1;" : "=f"(r) : "f"(x)); return r;
}
__device__ __forceinline__ float lg2(float x) {
    float r; asm("lg2.approx.f32 %0,%1;" : "=f"(r) : "f"(x)); return r;
}

__global__ __launch_bounds__(WPB * 32)
void rmloss_kernel(const float* __restrict__ logits,
                   float* __restrict__ out,
                   int n_seg)
{
    __shared__ float4 ring[WPB][64];   // (e0,e1,e2,e3) per lane, duplicated

    const int w    = threadIdx.x >> 5;
    const int lane = threadIdx.x & 31;
    const int gw   = blockIdx.x * WPB + w;
    const int s0   = gw * 4;                        // 4 segments per warp
    if (s0 >= n_seg) return;

    const float* base = logits + (size_t)s0 * 32 + lane;
    const float x0 = base[0],  x1 = base[32];
    const float x2 = base[64], x3 = base[96];

    // e = exp(x) * 2^-2 = exp2(x*log2e - 2).
    const float e0 = ex2(fmaf(x0, L2E, -2.0f));
    const float e1 = ex2(fmaf(x1, L2E, -2.0f));
    const float e2 = ex2(fmaf(x2, L2E, -2.0f));
    const float e3 = ex2(fmaf(x3, L2E, -2.0f));

    // Duplicated combined ring.
    const float4 ev = make_float4(e0, e1, e2, e3);
    ring[w][lane]      = ev;
    ring[w][lane + 32] = ev;
    __syncwarp();

    // Pair core: 16-term product per chain. Offsets 1..15 hit each unordered
    // pair exactly once; offset 16 only lanes 0..15 (upper half -> x1.0).
    // Loads batched 4 offsets at a time so LDS latency overlaps math.
    float p0, p1, p2, p3;
    {
        float4 a = ring[w][lane + 1];
        float4 b = ring[w][lane + 2];
        float4 c = ring[w][lane + 3];
        float4 d = ring[w][lane + 4];
        p0 = (e0 + a.x) * (e0 + b.x) * ((e0 + c.x) * (e0 + d.x));
        p1 = (e1 + a.y) * (e1 + b.y) * ((e1 + c.y) * (e1 + d.y));
        p2 = (e2 + a.z) * (e2 + b.z) * ((e2 + c.z) * (e2 + d.z));
        p3 = (e3 + a.w) * (e3 + b.w) * ((e3 + c.w) * (e3 + d.w));
    }
    #pragma unroll
    for (int ob = 5; ob <= 9; ob += 4) {            // batches {5-8}, {9-12}
        float4 a = ring[w][lane + ob];
        float4 b = ring[w][lane + ob + 1];
        float4 c = ring[w][lane + ob + 2];
        float4 d = ring[w][lane + ob + 3];
        p0 *= (e0 + a.x) * (e0 + b.x) * ((e0 + c.x) * (e0 + d.x));
        p1 *= (e1 + a.y) * (e1 + b.y) * ((e1 + c.y) * (e1 + d.y));
        p2 *= (e2 + a.z) * (e2 + b.z) * ((e2 + c.z) * (e2 + d.z));
        p3 *= (e3 + a.w) * (e3 + b.w) * ((e3 + c.w) * (e3 + d.w));
    }
    {   // final batch: offsets 13, 14, 15, and masked 16
        float4 a = ring[w][lane + 13];
        float4 b = ring[w][lane + 14];
        float4 c = ring[w][lane + 15];
        float4 d = ring[w][lane + 16];
        const bool lo16 = (lane < 16);
        p0 *= (e0 + a.x) * (e0 + b.x) * ((e0 + c.x) * (lo16 ? (e0 + d.x) : 1.0f));
        p1 *= (e1 + a.y) * (e1 + b.y) * ((e1 + c.y) * (lo16 ? (e1 + d.y) : 1.0f));
        p2 *= (e2 + a.z) * (e2 + b.z) * ((e2 + c.z) * (lo16 ? (e2 + d.z) : 1.0f));
        p3 *= (e3 + a.w) * (e3 + b.w) * ((e3 + c.w) * (lo16 ? (e3 + d.w) : 1.0f));
    }

    // Constants (all scale factors folded):
    //   partial = x*CL + x^2*CQ + CLN*[E + lg2(m)] + KPS
    const float CL  = (float)(31 - lane)     * (-INV_PAIRS);
    const float CQ  = (float)(31 - 2 * lane) * (-0.0005f * INV_PAIRS);
    const float CLN = LN2 * INV_PAIRS;
    const float KPS = CLN * (((lane < 16) ? 32.0f : 30.0f) - 127.0f);

    u32 b0 = __float_as_uint(p0), b1 = __float_as_uint(p1);
    u32 b2 = __float_as_uint(p2), b3 = __float_as_uint(p3);
    const float m0 = __uint_as_float((b0 & 0x007FFFFFu) | 0x3F800000u);
    const float m1 = __uint_as_float((b1 & 0x007FFFFFu) | 0x3F800000u);
    const float m2 = __uint_as_float((b2 & 0x007FFFFFu) | 0x3F800000u);
    const float m3 = __uint_as_float((b3 & 0x007FFFFFu) | 0x3F800000u);

    float t0 = fmaf((float)(int)(b0 >> 23), CLN, KPS);
    float t1 = fmaf((float)(int)(b1 >> 23), CLN, KPS);
    float t2 = fmaf((float)(int)(b2 >> 23), CLN, KPS);
    float t3 = fmaf((float)(int)(b3 >> 23), CLN, KPS);
    t0 = fmaf(lg2(m0), CLN, t0);
    t1 = fmaf(lg2(m1), CLN, t1);
    t2 = fmaf(lg2(m2), CLN, t2);
    t3 = fmaf(lg2(m3), CLN, t3);

    t0 = fmaf(x0, CL, t0);  t0 = fmaf(x0 * x0, CQ, t0);
    t1 = fmaf(x1, CL, t1);  t1 = fmaf(x1 * x1, CQ, t1);
    t2 = fmaf(x2, CL, t2);  t2 = fmaf(x2 * x2, CQ, t2);
    t3 = fmaf(x3, CL, t3);  t3 = fmaf(x3 * x3, CQ, t3);

    // Warp-level transpose reduction: store t-vector, then 8 lanes per
    // segment sum 4 strided elements each (conflict-free LDS.32), finish
    // with 3 shfl_xor inside 8-lane groups.
    __syncwarp();                       // pair-core ring reads complete
    ring[w][lane] = make_float4(t0, t1, t2, t3);
    __syncwarp();

    const int g   = lane >> 3;          // segment 0..3 within this warp
    const int idx = lane & 7;
    const float* rb = (const float*)&ring[w][0];   // 32 float4 = 128 floats
    float s = (rb[idx * 4 + g]        + rb[(idx +  8) * 4 + g])
            + (rb[(idx + 16) * 4 + g] + rb[(idx + 24) * 4 + g]);
    s += __shfl_xor_sync(0xFFFFFFFFu, s, 1);
    s += __shfl_xor_sync(0xFFFFFFFFu, s, 2);
    s += __shfl_xor_sync(0xFFFFFFFFu, s, 4);

    if (idx == 0)
        out[s0 + g] = s;                // lanes 0,8,16,24 -> 4 consecutive floats
}

extern "C" void kernel_launch(void* const* d_in, const int* in_sizes, int n_in,
                              void* d_out, int out_size)
{
    const float* logits = (const float*)d_in[0];
    float* out = (float*)d_out;
    const int n_seg = out_size;                  // 32768

    const int threads = WPB * 32;                // 256
    const int blocks = (n_seg + SEG_PER_BLOCK - 1) / SEG_PER_BLOCK;   // 1024
    rmloss_kernel<<<blocks, threads>>>(logits, out, n_seg);
}

// round 12
// speedup vs baseline: 1.0370x; 1.0333x over previous
#include <cuda_runtime.h>
#include <cuda_bf16.h>

// loss[s] = -(1/496)*[ sum_i x_i*(31-i) - sum_{i<j} ln(e_i+e_j) + 0.0005*sum_i x_i^2*(31-2i) ]
// via log_sigmoid(x_i - x_j) == x_i - ln(e^{x_i} + e^{x_j}).
//
// sum_{pairs} ln = ln(prod): per lane, two renorm-free 8-term fp32 products,
// ONE lg2 at the end. Fully scalar, 4 segments/warp as 4 independent chains,
// interleaved float2 rings (one LDS.64 feeds two chains).
//
// Launch shape: 64-thread blocks x 4096 CTAs -> up to 32 blocks/SM = 64
// resident warps/SM (regs=32 fills the RF exactly). Max warp supply is what
// converts to issue% on this latency-bound kernel.

static constexpr float INV_PAIRS = 1.0f / 496.0f;
static constexpr float LN2  = 0.69314718055994530942f;
static constexpr float L2E  = 1.44269504088896340736f;
static constexpr int   WPB  = 2;                 // warps per block (64 thr)
static constexpr int   SEG_PER_BLOCK = WPB * 4;  // 8

typedef unsigned int u32;

__device__ __forceinline__ float ex2(float x) {
    float r; asm("ex2.approx.f32 %0,%1;" : "=f"(r) : "f"(x)); return r;
}
__device__ __forceinline__ float lg2(float x) {
    float r; asm("lg2.approx.f32 %0,%1;" : "=f"(r) : "f"(x)); return r;
}
// ln(p*q)/496 where p,q are renorm-free partial products:
// CLN*[(Ep+Eq-254) + lg2(mp*mq)], mp*mq in [1,4).
__device__ __forceinline__ float scaled_log(float p, float q, float CLN) {
    u32 bp = __float_as_uint(p), bq = __float_as_uint(q);
    int  e  = (int)(bp >> 23) + (int)(bq >> 23) - 254;
    float mp = __uint_as_float((bp & 0x007FFFFFu) | 0x3F800000u);
    float mq = __uint_as_float((bq & 0x007FFFFFu) | 0x3F800000u);
    return fmaf((float)e, CLN, lg2(mp * mq) * CLN);
}

__global__ __launch_bounds__(WPB * 32, 32)
void rmloss_kernel(const float* __restrict__ logits,
                   float4* __restrict__ out,
                   int n_seg)
{
    __shared__ float2 r01[WPB][64];   // interleaved (seg0, seg1), duplicated ring
    __shared__ float2 r23[WPB][64];   // interleaved (seg2, seg3), duplicated ring

    const int w    = threadIdx.x >> 5;
    const int lane = threadIdx.x & 31;
    const int gw   = blockIdx.x * WPB + w;
    const int s0   = gw * 4;                        // 4 segments per warp
    if (s0 >= n_seg) return;

    const float* base = logits + (size_t)s0 * 32 + lane;
    const float x0 = base[0],  x1 = base[32];
    const float x2 = base[64], x3 = base[96];

    // e = exp(x) = exp2(x * log2e)
    const float e0 = ex2(x0 * L2E);
    const float e1 = ex2(x1 * L2E);
    const float e2 = ex2(x2 * L2E);
    const float e3 = ex2(x3 * L2E);

    // Duplicated interleaved rings -> pair reads are LDS.64 [base + imm].
    const float2 v01 = make_float2(e0, e1);
    const float2 v23 = make_float2(e2, e3);
    r01[w][lane] = v01;  r01[w][lane + 32] = v01;
    r23[w][lane] = v23;  r23[w][lane + 32] = v23;
    __syncwarp();

    // Products of pair terms (e_l + e_{l+o}). Offsets 1..15 hit each unordered
    // pair exactly once; offset 16 only for lanes 0..15. Two 8-term
    // accumulators per segment: renorm-free (<= 2^+-72).
    float2 a = r01[w][lane + 1], b = r23[w][lane + 1];
    float pa0 = e0 + a.x, pa1 = e1 + a.y, pa2 = e2 + b.x, pa3 = e3 + b.y;
    #pragma unroll
    for (int o = 2; o <= 8; ++o) {
        a = r01[w][lane + o];  b = r23[w][lane + o];
        pa0 *= e0 + a.x;  pa1 *= e1 + a.y;
        pa2 *= e2 + b.x;  pa3 *= e3 + b.y;
    }
    a = r01[w][lane + 9];  b = r23[w][lane + 9];
    float pb0 = e0 + a.x, pb1 = e1 + a.y, pb2 = e2 + b.x, pb3 = e3 + b.y;
    #pragma unroll
    for (int o = 10; o <= 15; ++o) {
        a = r01[w][lane + o];  b = r23[w][lane + o];
        pb0 *= e0 + a.x;  pb1 *= e1 + a.y;
        pb2 *= e2 + b.x;  pb3 *= e3 + b.y;
    }
    {   // offset 16: lanes >= 16 contribute a factor of 1.0 (FSEL, no branch)
        a = r01[w][lane + 16];  b = r23[w][lane + 16];
        const bool m = (lane < 16);
        pb0 *= m ? (e0 + a.x) : 1.0f;
        pb1 *= m ? (e1 + a.y) : 1.0f;
        pb2 *= m ? (e2 + b.x) : 1.0f;
        pb3 *= m ? (e3 + b.y) : 1.0f;
    }

    // Per-lane coefficients with all scale factors folded in:
    //   v = x*(-(31-l)/496) + x^2*(-0.0005*(31-2l)/496) + ln(prod)/496
    const float CL  = (float)(31 - lane)     * (-INV_PAIRS);
    const float CQ  = (float)(31 - 2 * lane) * (-0.0005f * INV_PAIRS);
    const float CLN = LN2 * INV_PAIRS;

    float t0 = scaled_log(pa0, pb0, CLN);
    float t1 = scaled_log(pa1, pb1, CLN);
    float t2 = scaled_log(pa2, pb2, CLN);
    float t3 = scaled_log(pa3, pb3, CLN);

    t0 = fmaf(x0, CL, t0);  t0 = fmaf(x0 * x0, CQ, t0);
    t1 = fmaf(x1, CL, t1);  t1 = fmaf(x1 * x1, CQ, t1);
    t2 = fmaf(x2, CL, t2);  t2 = fmaf(x2 * x2, CQ, t2);
    t3 = fmaf(x3, CL, t3);  t3 = fmaf(x3 * x3, CQ, t3);

    // Butterfly reduction: 4 independent scalar chains.
    #pragma unroll
    for (int m = 16; m >= 1; m >>= 1) {
        t0 += __shfl_xor_sync(0xFFFFFFFFu, t0, m);
        t1 += __shfl_xor_sync(0xFFFFFFFFu, t1, m);
        t2 += __shfl_xor_sync(0xFFFFFFFFu, t2, m);
        t3 += __shfl_xor_sync(0xFFFFFFFFu, t3, m);
    }

    if (lane == 0)
        out[gw] = make_float4(t0, t1, t2, t3);   // STG.128, coalesced
}

extern "C" void kernel_launch(void* const* d_in, const int* in_sizes, int n_in,
                              void* d_out, int out_size)
{
    const float* logits = (const float*)d_in[0];
    float4* out = (float4*)d_out;
    const int n_seg = out_size;                  // 32768

    const int threads = WPB * 32;                // 64
    const int blocks = (n_seg + SEG_PER_BLOCK - 1) / SEG_PER_BLOCK;   // 4096
    rmloss_kernel<<<blocks, threads>>>(logits, out, n_seg);
}